// round 10
// baseline (speedup 1.0000x reference)
#include <cuda_runtime.h>
#include <math.h>

#define NG     128
#define NPER   512
#define NNODE  (NG*NPER)      // 65536
#define NEDGE  1048576
#define KTOP   30
#define DNODE  64
#define DEDGE  32
#define D0     96
#define DL     32
#define HSTRIDE 96
#define TOTALF 97
#define C1N    16
#define C2N    32
#define KW     5
#define PLEN   15
#define CONVL  11
#define DENSE  352
#define OUTD   128
#define BCAP   96             // per-node bucket capacity (deg ~ Poisson(16))

// ---------------- scratch ----------------
__device__ float  g_zA [NNODE*DL];
__device__ float  g_zB [NNODE*DL];
__device__ float  g_z3 [NNODE];
__device__ float  g_hcat[NNODE*HSTRIDE];
__device__ int    g_cnt [NNODE];
__device__ int2   g_pair[NNODE*BCAP];   // .x = src*128 (z-row byte off), .y = eid*128 (ef-row byte off)

__device__ __forceinline__ float* zsel(int s) { return s == 0 ? g_zA : g_zB; }

// load 8 pre-scaled offsets (component sel: 0 -> .x/.z (src), 1 -> .y/.w (eid))
#define LOAD8(OFS, SEL)                                                     \
    {                                                                       \
        const int4* p4 = (const int4*)(g_pair + j);                         \
        int4 q0 = p4[0], q1 = p4[1], q2 = p4[2], q3 = p4[3];                \
        if (SEL) {                                                          \
            OFS[0]=q0.y; OFS[1]=q0.w; OFS[2]=q1.y; OFS[3]=q1.w;             \
            OFS[4]=q2.y; OFS[5]=q2.w; OFS[6]=q3.y; OFS[7]=q3.w;             \
        } else {                                                            \
            OFS[0]=q0.x; OFS[1]=q0.z; OFS[2]=q1.x; OFS[3]=q1.z;             \
            OFS[4]=q2.x; OFS[5]=q2.z; OFS[6]=q3.x; OFS[7]=q3.z;             \
        }                                                                   \
    }

// ---------------- bucket CSR build: one atomic per edge ----------------
__global__ void k_fillb(const int* __restrict__ src, const int* __restrict__ dst) {
    int i = blockIdx.x * 1024 + threadIdx.x;
    int4 d = ((const int4*)dst)[i];
    int4 s = ((const int4*)src)[i];
    int e = i * 4;
    int p0 = atomicAdd(&g_cnt[d.x], 1);
    if (p0 < BCAP) g_pair[d.x * BCAP + p0] = make_int2(s.x << 7, e << 7);
    int p1 = atomicAdd(&g_cnt[d.y], 1);
    if (p1 < BCAP) g_pair[d.y * BCAP + p1] = make_int2(s.y << 7, (e + 1) << 7);
    int p2 = atomicAdd(&g_cnt[d.z], 1);
    if (p2 < BCAP) g_pair[d.z * BCAP + p2] = make_int2(s.z << 7, (e + 2) << 7);
    int p3 = atomicAdd(&g_cnt[d.w], 1);
    if (p3 < BCAP) g_pair[d.w * BCAP + p3] = make_int2(s.w << 7, (e + 3) << 7);
}

// ---------------- build z0 = [nf | e2n] @ W0 ----------------
__global__ void k_build0(const float* __restrict__ nf, const float* __restrict__ ef,
                         const float* __restrict__ W0) {
    __shared__ float Ws[D0 * DL];
    __shared__ float agg[8][D0];
    int tid = threadIdx.x;
    for (int i = tid; i < D0 * DL; i += 256) Ws[i] = W0[i];
    __syncthreads();
    int w = tid >> 5, lane = tid & 31;
    int n = blockIdx.x * 8 + w;
    float f0 = nf[n * DNODE + lane];
    float f1 = nf[n * DNODE + 32 + lane];
    const char* eb = (const char*)ef + (lane << 2);
    int beg = n * BCAP, end = beg + g_cnt[n];
    float acc0 = 0.f, acc1 = 0.f;
    int j = beg;
    for (; j + 15 < end; j += 16) {
        int o[8], o2[8];
        LOAD8(o, 1)
        { const int4* p4 = (const int4*)(g_pair + j + 8);
          int4 q0 = p4[0], q1 = p4[1], q2 = p4[2], q3 = p4[3];
          o2[0]=q0.y; o2[1]=q0.w; o2[2]=q1.y; o2[3]=q1.w;
          o2[4]=q2.y; o2[5]=q2.w; o2[6]=q3.y; o2[7]=q3.w; }
        float v0 = *(const float*)(eb + o[0]);
        float v1 = *(const float*)(eb + o[1]);
        float v2 = *(const float*)(eb + o[2]);
        float v3 = *(const float*)(eb + o[3]);
        float v4 = *(const float*)(eb + o[4]);
        float v5 = *(const float*)(eb + o[5]);
        float v6 = *(const float*)(eb + o[6]);
        float v7 = *(const float*)(eb + o[7]);
        float u0 = *(const float*)(eb + o2[0]);
        float u1 = *(const float*)(eb + o2[1]);
        float u2 = *(const float*)(eb + o2[2]);
        float u3 = *(const float*)(eb + o2[3]);
        float u4 = *(const float*)(eb + o2[4]);
        float u5 = *(const float*)(eb + o2[5]);
        float u6 = *(const float*)(eb + o2[6]);
        float u7 = *(const float*)(eb + o2[7]);
        acc0 += ((v0 + v1) + (v2 + v3)) + ((v4 + v5) + (v6 + v7));
        acc1 += ((u0 + u1) + (u2 + u3)) + ((u4 + u5) + (u6 + u7));
    }
    for (; j + 7 < end; j += 8) {
        int o[8];
        LOAD8(o, 1)
        float v0 = *(const float*)(eb + o[0]);
        float v1 = *(const float*)(eb + o[1]);
        float v2 = *(const float*)(eb + o[2]);
        float v3 = *(const float*)(eb + o[3]);
        float v4 = *(const float*)(eb + o[4]);
        float v5 = *(const float*)(eb + o[5]);
        float v6 = *(const float*)(eb + o[6]);
        float v7 = *(const float*)(eb + o[7]);
        acc0 += ((v0 + v1) + (v2 + v3)) + ((v4 + v5) + (v6 + v7));
    }
    for (; j < end; j++) acc0 += *(const float*)(eb + g_pair[j].y);
    agg[w][lane] = f0; agg[w][32 + lane] = f1; agg[w][64 + lane] = acc0 + acc1;
    __syncwarp();
    float z = 0.f;
#pragma unroll
    for (int d = 0; d < D0; d++) z += agg[w][d] * Ws[d * DL + lane];
    g_zA[n * DL + lane] = z;
}

// ---------------- gather z + tanh + project to next z (32->32) ----------------
__global__ void k_gather32(int insel, int outsel, int hcat_off,
                           const float* __restrict__ b, const float* __restrict__ Wn) {
    __shared__ float Ws[DL * DL];
    __shared__ float bs[DL];
    __shared__ float vals[8][DL];
    int tid = threadIdx.x;
    for (int i = tid; i < DL * DL; i += 256) Ws[i] = Wn[i];
    if (tid < DL) bs[tid] = b[tid];
    __syncthreads();
    int w = tid >> 5, lane = tid & 31;
    int n = blockIdx.x * 8 + w;
    const float* z = zsel(insel);
    const char* zb = (const char*)z + (lane << 2);
    float a = z[n * DL + lane];
    int cnt = g_cnt[n];
    int beg = n * BCAP, end = beg + cnt;
    int j = beg;
    for (; j + 7 < end; j += 8) {
        int o[8];
        LOAD8(o, 0)
        float x0 = *(const float*)(zb + o[0]);
        float x1 = *(const float*)(zb + o[1]);
        float x2 = *(const float*)(zb + o[2]);
        float x3 = *(const float*)(zb + o[3]);
        float x4 = *(const float*)(zb + o[4]);
        float x5 = *(const float*)(zb + o[5]);
        float x6 = *(const float*)(zb + o[6]);
        float x7 = *(const float*)(zb + o[7]);
        a += ((x0 + x1) + (x2 + x3)) + ((x4 + x5) + (x6 + x7));
    }
    for (; j < end; j++) a += *(const float*)(zb + g_pair[j].x);
    float val = tanhf((a + bs[lane]) / ((float)cnt + 1.f));
    g_hcat[n * HSTRIDE + hcat_off + lane] = val;
    vals[w][lane] = val;
    __syncwarp();
    float zn = 0.f;
#pragma unroll
    for (int d = 0; d < DL; d++) zn += vals[w][d] * Ws[d * DL + lane];
    zsel(outsel)[n * DL + lane] = zn;
}

// ---------------- gather z + tanh + project to scalar (32->1) ----------------
__global__ void k_gather_p1(int insel, const float* __restrict__ b,
                            const float* __restrict__ W3) {
    int tid = threadIdx.x;
    int w = tid >> 5, lane = tid & 31;
    int n = blockIdx.x * 8 + w;
    const float* z = zsel(insel);
    const char* zb = (const char*)z + (lane << 2);
    float a = z[n * DL + lane];
    int cnt = g_cnt[n];
    int beg = n * BCAP, end = beg + cnt;
    int j = beg;
    for (; j + 7 < end; j += 8) {
        int o[8];
        LOAD8(o, 0)
        float x0 = *(const float*)(zb + o[0]);
        float x1 = *(const float*)(zb + o[1]);
        float x2 = *(const float*)(zb + o[2]);
        float x3 = *(const float*)(zb + o[3]);
        float x4 = *(const float*)(zb + o[4]);
        float x5 = *(const float*)(zb + o[5]);
        float x6 = *(const float*)(zb + o[6]);
        float x7 = *(const float*)(zb + o[7]);
        a += ((x0 + x1) + (x2 + x3)) + ((x4 + x5) + (x6 + x7));
    }
    for (; j < end; j++) a += *(const float*)(zb + g_pair[j].x);
    float val = tanhf((a + b[lane]) / ((float)cnt + 1.f));
    g_hcat[n * HSTRIDE + 64 + lane] = val;
    float v = val * W3[lane];
#pragma unroll
    for (int off = 16; off > 0; off >>= 1) v += __shfl_xor_sync(0xffffffffu, v, off);
    if (lane == 0) g_z3[n] = v;
}

// ---------------- fused: ch96 gather + topk + head ----------------
__global__ void k_tail(const float* __restrict__ b3,
                       const float* __restrict__ cw1, const float* __restrict__ cb1,
                       const float* __restrict__ cw2, const float* __restrict__ cb2,
                       const float* __restrict__ ow,  const float* __restrict__ ob,
                       float* __restrict__ out) {
    __shared__ float ch96[NPER];
    __shared__ float v[NPER];
    __shared__ int   ix[NPER];
    __shared__ float pooled[KTOP][TOTALF];
    __shared__ float c1s[C1N][KTOP];
    __shared__ float c1p[C1N][PLEN];
    __shared__ float c2s[DENSE];
    int g = blockIdx.x, tid = threadIdx.x;      // 256 threads
    const char* z3b = (const char*)g_z3;

    // ---- channel 96: scalar gather of z3 (offset = pair.x>>5) ----
    float bb = b3[0];
#pragma unroll
    for (int half = 0; half < 2; half++) {
        int i = tid + half * 256;
        int n = g * NPER + i;
        float a = g_z3[n];
        int cnt = g_cnt[n];
        int beg = n * BCAP, end = beg + cnt;
        int j = beg;
        float a1 = 0.f, a2 = 0.f, a3 = 0.f;
        for (; j + 3 < end; j += 4) {
            a  += *(const float*)(z3b + (g_pair[j].x   >> 5));
            a1 += *(const float*)(z3b + (g_pair[j+1].x >> 5));
            a2 += *(const float*)(z3b + (g_pair[j+2].x >> 5));
            a3 += *(const float*)(z3b + (g_pair[j+3].x >> 5));
        }
        for (; j < end; j++) a += *(const float*)(z3b + (g_pair[j].x >> 5));
        a = (a + a1) + (a2 + a3);
        float cv = tanhf((a + bb) / ((float)cnt + 1.f));
        ch96[i] = cv;
        v[i] = cv;
        ix[i] = i;
    }
    __syncthreads();

    // ---- bitonic top-K (value desc, index asc ties) ----
    for (int k = 2; k <= NPER; k <<= 1) {
        for (int j = k >> 1; j > 0; j >>= 1) {
            for (int i = tid; i < NPER; i += 256) {
                int p = i ^ j;
                if (p > i) {
                    float va = v[i], vb = v[p];
                    int ia = ix[i], ib = ix[p];
                    bool a_first = (va > vb) || (va == vb && ia < ib);
                    bool up = ((i & k) == 0);
                    if (up ? !a_first : a_first) {
                        v[i] = vb; v[p] = va;
                        ix[i] = ib; ix[p] = ia;
                    }
                }
            }
            __syncthreads();
        }
    }

    // ---- gather pooled ----
    for (int t = tid; t < KTOP * HSTRIDE; t += 256) {
        int kk = t / HSTRIDE, d = t - kk * HSTRIDE;
        int node = g * NPER + ix[kk];
        pooled[kk][d] = g_hcat[node * HSTRIDE + d];
    }
    if (tid < KTOP) pooled[tid][96] = ch96[ix[tid]];
    __syncthreads();

    // ---- 1x1 conv + relu ----
    for (int t = tid; t < C1N * KTOP; t += 256) {
        int o = t / KTOP, kk = t - o * KTOP;
        float s = cb1[o];
#pragma unroll 8
        for (int d = 0; d < TOTALF; d++) s += pooled[kk][d] * cw1[o * TOTALF + d];
        c1s[o][kk] = fmaxf(s, 0.f);
    }
    __syncthreads();

    // ---- maxpool /2 ----
    for (int t = tid; t < C1N * PLEN; t += 256) {
        int o = t / PLEN, j = t - o * PLEN;
        c1p[o][j] = fmaxf(c1s[o][2 * j], c1s[o][2 * j + 1]);
    }
    __syncthreads();

    // ---- conv k=5 + relu ----
    for (int t = tid; t < C2N * CONVL; t += 256) {
        int o = t / CONVL, j = t - o * CONVL;
        float s = cb2[o];
#pragma unroll
        for (int i = 0; i < C1N; i++)
#pragma unroll
            for (int u = 0; u < KW; u++)
                s += c1p[i][j + u] * cw2[(o * C1N + i) * KW + u];
        c2s[o * CONVL + j] = fmaxf(s, 0.f);
    }
    __syncthreads();

    // ---- dense 352->128 + relu ----
    if (tid < OUTD) {
        int u = tid;
        float s = ob[u];
#pragma unroll 8
        for (int f = 0; f < DENSE; f++) s += c2s[f] * ow[f * OUTD + u];
        out[g * OUTD + u] = fmaxf(s, 0.f);
    }
}

// ---------------- launch ----------------
extern "C" void kernel_launch(void* const* d_in, const int* in_sizes, int n_in,
                              void* d_out, int out_size) {
    const float* node_feat = (const float*)d_in[0];
    const float* edge_feat = (const float*)d_in[1];
    const int*   edge_src  = (const int*)  d_in[2];
    const int*   edge_dst  = (const int*)  d_in[3];
    const float* W0 = (const float*)d_in[4];
    const float* b0 = (const float*)d_in[5];
    const float* W1 = (const float*)d_in[6];
    const float* b1 = (const float*)d_in[7];
    const float* W2 = (const float*)d_in[8];
    const float* b2 = (const float*)d_in[9];
    const float* W3 = (const float*)d_in[10];
    const float* b3 = (const float*)d_in[11];
    const float* cw1 = (const float*)d_in[12];
    const float* cb1 = (const float*)d_in[13];
    const float* cw2 = (const float*)d_in[14];
    const float* cb2 = (const float*)d_in[15];
    const float* ow  = (const float*)d_in[16];
    const float* ob  = (const float*)d_in[17];
    float* out = (float*)d_out;

    void* cnt_ptr = nullptr;
    cudaGetSymbolAddress(&cnt_ptr, g_cnt);
    cudaMemsetAsync(cnt_ptr, 0, NNODE * sizeof(int), 0);

    k_fillb<<<NEDGE / 4096, 1024>>>(edge_src, edge_dst);

    k_build0   <<<NNODE / 8, 256>>>(node_feat, edge_feat, W0);  // -> zA
    k_gather32 <<<NNODE / 8, 256>>>(0, 1, 0,  b0, W1);          // zA -> hcat0, zB
    k_gather32 <<<NNODE / 8, 256>>>(1, 0, 32, b1, W2);          // zB -> hcat32, zA
    k_gather_p1<<<NNODE / 8, 256>>>(0, b2, W3);                 // zA -> hcat64, z3

    k_tail<<<NG, 256>>>(b3, cw1, cb1, cw2, cb2, ow, ob, out);
}

// round 11
// speedup vs baseline: 1.0629x; 1.0629x over previous
#include <cuda_runtime.h>
#include <math.h>

#define NG     128
#define NPER   512
#define NNODE  (NG*NPER)      // 65536
#define NEDGE  1048576
#define KTOP   30
#define DNODE  64
#define DEDGE  32
#define D0     96
#define DL     32
#define HSTRIDE 96
#define TOTALF 97
#define C1N    16
#define C2N    32
#define KW     5
#define PLEN   15
#define CONVL  11
#define DENSE  352
#define OUTD   128
#define BCAP   96             // per-node bucket capacity (deg ~ Poisson(16))
#define FULLM  0xffffffffu

// ---------------- scratch ----------------
__device__ float  g_zA [NNODE*DL];
__device__ float  g_zB [NNODE*DL];
__device__ float  g_z3 [NNODE];
__device__ float  g_hcat[NNODE*HSTRIDE];
__device__ int    g_cnt [NNODE];
__device__ int2   g_pair[NNODE*BCAP];   // .x = src node, .y = edge id

__device__ __forceinline__ float* zsel(int s) { return s == 0 ? g_zA : g_zB; }

// ---------------- bucket CSR build: one atomic per edge ----------------
__global__ void k_fillb(const int* __restrict__ src, const int* __restrict__ dst) {
    int i = blockIdx.x * 1024 + threadIdx.x;
    int4 d = ((const int4*)dst)[i];
    int4 s = ((const int4*)src)[i];
    int e = i * 4;
    int p0 = atomicAdd(&g_cnt[d.x], 1);
    if (p0 < BCAP) g_pair[d.x * BCAP + p0] = make_int2(s.x, e);
    int p1 = atomicAdd(&g_cnt[d.y], 1);
    if (p1 < BCAP) g_pair[d.y * BCAP + p1] = make_int2(s.y, e + 1);
    int p2 = atomicAdd(&g_cnt[d.z], 1);
    if (p2 < BCAP) g_pair[d.z * BCAP + p2] = make_int2(s.z, e + 2);
    int p3 = atomicAdd(&g_cnt[d.w], 1);
    if (p3 < BCAP) g_pair[d.w * BCAP + p3] = make_int2(s.w, e + 3);
}

// warp-cooperative gather-sum over 32-float rows: indices fetched once per
// 32-neighbor chunk via coalesced load, broadcast by shfl. Accumulates into a.
#define WGATHER(BASEPTR, COMP)                                              \
    for (int cbase = 0; cbase < cnt; cbase += 32) {                         \
        int rem = cnt - cbase; if (rem > 32) rem = 32;                      \
        int myidx = (lane < rem) ? g_pair[beg + cbase + lane].COMP : 0;     \
        int t = 0;                                                          \
        for (; t + 7 < rem; t += 8) {                                       \
            int s0 = __shfl_sync(FULLM, myidx, t);                          \
            int s1 = __shfl_sync(FULLM, myidx, t + 1);                      \
            int s2 = __shfl_sync(FULLM, myidx, t + 2);                      \
            int s3 = __shfl_sync(FULLM, myidx, t + 3);                      \
            int s4 = __shfl_sync(FULLM, myidx, t + 4);                      \
            int s5 = __shfl_sync(FULLM, myidx, t + 5);                      \
            int s6 = __shfl_sync(FULLM, myidx, t + 6);                      \
            int s7 = __shfl_sync(FULLM, myidx, t + 7);                      \
            float x0 = BASEPTR[s0 * 32 + lane];                             \
            float x1 = BASEPTR[s1 * 32 + lane];                             \
            float x2 = BASEPTR[s2 * 32 + lane];                             \
            float x3 = BASEPTR[s3 * 32 + lane];                             \
            float x4 = BASEPTR[s4 * 32 + lane];                             \
            float x5 = BASEPTR[s5 * 32 + lane];                             \
            float x6 = BASEPTR[s6 * 32 + lane];                             \
            float x7 = BASEPTR[s7 * 32 + lane];                             \
            a += ((x0 + x1) + (x2 + x3)) + ((x4 + x5) + (x6 + x7));         \
        }                                                                   \
        for (; t < rem; t++) {                                              \
            int ss = __shfl_sync(FULLM, myidx, t);                          \
            a += BASEPTR[ss * 32 + lane];                                   \
        }                                                                   \
    }

// ---------------- build z0 = [nf | e2n] @ W0 ----------------
__global__ void k_build0(const float* __restrict__ nf, const float* __restrict__ ef,
                         const float* __restrict__ W0) {
    __shared__ float Ws[D0 * DL];
    __shared__ float agg[8][D0];
    int tid = threadIdx.x;
    for (int i = tid; i < D0 * DL; i += 256) Ws[i] = W0[i];
    __syncthreads();
    int w = tid >> 5, lane = tid & 31;
    int n = blockIdx.x * 8 + w;
    float f0 = nf[n * DNODE + lane];
    float f1 = nf[n * DNODE + 32 + lane];
    int cnt = g_cnt[n]; if (cnt > BCAP) cnt = BCAP;
    int beg = n * BCAP;
    float a = 0.f;
    WGATHER(ef, y)
    agg[w][lane] = f0; agg[w][32 + lane] = f1; agg[w][64 + lane] = a;
    __syncwarp();
    float z = 0.f;
#pragma unroll
    for (int d = 0; d < D0; d++) z += agg[w][d] * Ws[d * DL + lane];
    g_zA[n * DL + lane] = z;
}

// ---------------- gather z + tanh + project to next z (32->32) ----------------
__global__ void k_gather32(int insel, int outsel, int hcat_off,
                           const float* __restrict__ b, const float* __restrict__ Wn) {
    __shared__ float Ws[DL * DL];
    __shared__ float bs[DL];
    __shared__ float vals[8][DL];
    int tid = threadIdx.x;
    for (int i = tid; i < DL * DL; i += 256) Ws[i] = Wn[i];
    if (tid < DL) bs[tid] = b[tid];
    __syncthreads();
    int w = tid >> 5, lane = tid & 31;
    int n = blockIdx.x * 8 + w;
    const float* z = zsel(insel);
    float a = z[n * DL + lane];
    int cnt = g_cnt[n]; if (cnt > BCAP) cnt = BCAP;
    int beg = n * BCAP;
    WGATHER(z, x)
    float val = tanhf((a + bs[lane]) / ((float)cnt + 1.f));
    g_hcat[n * HSTRIDE + hcat_off + lane] = val;
    vals[w][lane] = val;
    __syncwarp();
    float zn = 0.f;
#pragma unroll
    for (int d = 0; d < DL; d++) zn += vals[w][d] * Ws[d * DL + lane];
    zsel(outsel)[n * DL + lane] = zn;
}

// ---------------- gather z + tanh + project to scalar (32->1) ----------------
__global__ void k_gather_p1(int insel, const float* __restrict__ b,
                            const float* __restrict__ W3) {
    int tid = threadIdx.x;
    int w = tid >> 5, lane = tid & 31;
    int n = blockIdx.x * 8 + w;
    const float* z = zsel(insel);
    float a = z[n * DL + lane];
    int cnt = g_cnt[n]; if (cnt > BCAP) cnt = BCAP;
    int beg = n * BCAP;
    WGATHER(z, x)
    float val = tanhf((a + b[lane]) / ((float)cnt + 1.f));
    g_hcat[n * HSTRIDE + 64 + lane] = val;
    float v = val * W3[lane];
#pragma unroll
    for (int off = 16; off > 0; off >>= 1) v += __shfl_xor_sync(FULLM, v, off);
    if (lane == 0) g_z3[n] = v;
}

// ---------------- fused: ch96 gather + topk + head ----------------
__global__ void k_tail(const float* __restrict__ b3,
                       const float* __restrict__ cw1, const float* __restrict__ cb1,
                       const float* __restrict__ cw2, const float* __restrict__ cb2,
                       const float* __restrict__ ow,  const float* __restrict__ ob,
                       float* __restrict__ out) {
    __shared__ float ch96[NPER];
    __shared__ float v[NPER];
    __shared__ int   ix[NPER];
    __shared__ float pooled[KTOP][TOTALF];
    __shared__ float c1s[C1N][KTOP];
    __shared__ float c1p[C1N][PLEN];
    __shared__ float c2s[DENSE];
    int g = blockIdx.x, tid = threadIdx.x;      // 256 threads

    // ---- channel 96: scalar gather of z3 over neighbors ----
    float bb = b3[0];
#pragma unroll
    for (int half = 0; half < 2; half++) {
        int i = tid + half * 256;
        int n = g * NPER + i;
        float a = g_z3[n];
        int cnt = g_cnt[n]; if (cnt > BCAP) cnt = BCAP;
        int beg = n * BCAP, end = beg + cnt;
        int j = beg;
        float a1 = 0.f, a2 = 0.f, a3 = 0.f;
        for (; j + 3 < end; j += 4) {
            a  += g_z3[g_pair[j].x];
            a1 += g_z3[g_pair[j+1].x];
            a2 += g_z3[g_pair[j+2].x];
            a3 += g_z3[g_pair[j+3].x];
        }
        for (; j < end; j++) a += g_z3[g_pair[j].x];
        a = (a + a1) + (a2 + a3);
        float cv = tanhf((a + bb) / ((float)cnt + 1.f));
        ch96[i] = cv;
        v[i] = cv;
        ix[i] = i;
    }
    __syncthreads();

    // ---- bitonic top-K (value desc, index asc ties) ----
    for (int k = 2; k <= NPER; k <<= 1) {
        for (int j = k >> 1; j > 0; j >>= 1) {
            for (int i = tid; i < NPER; i += 256) {
                int p = i ^ j;
                if (p > i) {
                    float va = v[i], vb = v[p];
                    int ia = ix[i], ib = ix[p];
                    bool a_first = (va > vb) || (va == vb && ia < ib);
                    bool up = ((i & k) == 0);
                    if (up ? !a_first : a_first) {
                        v[i] = vb; v[p] = va;
                        ix[i] = ib; ix[p] = ia;
                    }
                }
            }
            __syncthreads();
        }
    }

    // ---- gather pooled (ch 0..95 from hcat, ch96 from shared) ----
    for (int t = tid; t < KTOP * HSTRIDE; t += 256) {
        int kk = t / HSTRIDE, d = t - kk * HSTRIDE;
        int node = g * NPER + ix[kk];
        pooled[kk][d] = g_hcat[node * HSTRIDE + d];
    }
    if (tid < KTOP) pooled[tid][96] = ch96[ix[tid]];
    __syncthreads();

    // ---- 1x1 conv + relu ----
    for (int t = tid; t < C1N * KTOP; t += 256) {
        int o = t / KTOP, kk = t - o * KTOP;
        float s = cb1[o];
#pragma unroll 8
        for (int d = 0; d < TOTALF; d++) s += pooled[kk][d] * cw1[o * TOTALF + d];
        c1s[o][kk] = fmaxf(s, 0.f);
    }
    __syncthreads();

    // ---- maxpool /2 ----
    for (int t = tid; t < C1N * PLEN; t += 256) {
        int o = t / PLEN, j = t - o * PLEN;
        c1p[o][j] = fmaxf(c1s[o][2 * j], c1s[o][2 * j + 1]);
    }
    __syncthreads();

    // ---- conv k=5 + relu ----
    for (int t = tid; t < C2N * CONVL; t += 256) {
        int o = t / CONVL, j = t - o * CONVL;
        float s = cb2[o];
#pragma unroll
        for (int i = 0; i < C1N; i++)
#pragma unroll
            for (int u = 0; u < KW; u++)
                s += c1p[i][j + u] * cw2[(o * C1N + i) * KW + u];
        c2s[o * CONVL + j] = fmaxf(s, 0.f);
    }
    __syncthreads();

    // ---- dense 352->128 + relu ----
    if (tid < OUTD) {
        int u = tid;
        float s = ob[u];
#pragma unroll 8
        for (int f = 0; f < DENSE; f++) s += c2s[f] * ow[f * OUTD + u];
        out[g * OUTD + u] = fmaxf(s, 0.f);
    }
}

// ---------------- launch ----------------
extern "C" void kernel_launch(void* const* d_in, const int* in_sizes, int n_in,
                              void* d_out, int out_size) {
    const float* node_feat = (const float*)d_in[0];
    const float* edge_feat = (const float*)d_in[1];
    const int*   edge_src  = (const int*)  d_in[2];
    const int*   edge_dst  = (const int*)  d_in[3];
    const float* W0 = (const float*)d_in[4];
    const float* b0 = (const float*)d_in[5];
    const float* W1 = (const float*)d_in[6];
    const float* b1 = (const float*)d_in[7];
    const float* W2 = (const float*)d_in[8];
    const float* b2 = (const float*)d_in[9];
    const float* W3 = (const float*)d_in[10];
    const float* b3 = (const float*)d_in[11];
    const float* cw1 = (const float*)d_in[12];
    const float* cb1 = (const float*)d_in[13];
    const float* cw2 = (const float*)d_in[14];
    const float* cb2 = (const float*)d_in[15];
    const float* ow  = (const float*)d_in[16];
    const float* ob  = (const float*)d_in[17];
    float* out = (float*)d_out;

    void* cnt_ptr = nullptr;
    cudaGetSymbolAddress(&cnt_ptr, g_cnt);
    cudaMemsetAsync(cnt_ptr, 0, NNODE * sizeof(int), 0);

    k_fillb<<<NEDGE / 4096, 1024>>>(edge_src, edge_dst);

    k_build0   <<<NNODE / 8, 256>>>(node_feat, edge_feat, W0);  // -> zA
    k_gather32 <<<NNODE / 8, 256>>>(0, 1, 0,  b0, W1);          // zA -> hcat0, zB
    k_gather32 <<<NNODE / 8, 256>>>(1, 0, 32, b1, W2);          // zB -> hcat32, zA
    k_gather_p1<<<NNODE / 8, 256>>>(0, b2, W3);                 // zA -> hcat64, z3

    k_tail<<<NG, 256>>>(b3, cw1, cb1, cw2, cb2, ow, ob, out);
}

// round 12
// speedup vs baseline: 1.0858x; 1.0216x over previous
#include <cuda_runtime.h>
#include <math.h>

#define NG     128
#define NPER   512
#define NNODE  (NG*NPER)      // 65536
#define NEDGE  1048576
#define KTOP   30
#define DNODE  64
#define DEDGE  32
#define D0     96
#define DL     32
#define HSTRIDE 96
#define TOTALF 97
#define C1N    16
#define C2N    32
#define KW     5
#define PLEN   15
#define CONVL  11
#define DENSE  352
#define OUTD   128
#define BCAP   96             // per-node bucket capacity (deg ~ Poisson(16))
#define FULLM  0xffffffffu

// ---------------- scratch ----------------
__device__ float  g_zA [NNODE*DL];
__device__ float  g_zB [NNODE*DL];
__device__ float  g_z3 [NNODE];
__device__ float  g_hcat[NNODE*HSTRIDE];
__device__ int    g_cnt [NNODE];
__device__ int2   g_pair[NNODE*BCAP];   // .x = src node, .y = edge id

__device__ __forceinline__ float* zsel(int s) { return s == 0 ? g_zA : g_zB; }

// ---------------- bucket CSR build: one atomic per edge ----------------
__global__ void k_fillb(const int* __restrict__ src, const int* __restrict__ dst) {
    int i = blockIdx.x * 1024 + threadIdx.x;
    int4 d = ((const int4*)dst)[i];
    int4 s = ((const int4*)src)[i];
    int e = i * 4;
    int p0 = atomicAdd(&g_cnt[d.x], 1);
    if (p0 < BCAP) g_pair[d.x * BCAP + p0] = make_int2(s.x, e);
    int p1 = atomicAdd(&g_cnt[d.y], 1);
    if (p1 < BCAP) g_pair[d.y * BCAP + p1] = make_int2(s.y, e + 1);
    int p2 = atomicAdd(&g_cnt[d.z], 1);
    if (p2 < BCAP) g_pair[d.z * BCAP + p2] = make_int2(s.z, e + 2);
    int p3 = atomicAdd(&g_cnt[d.w], 1);
    if (p3 < BCAP) g_pair[d.w * BCAP + p3] = make_int2(s.w, e + 3);
}

// Dual-neighbor warp gather over 32-float rows.
// lanes 0-15 (half=0) accumulate even-positioned neighbors, lanes 16-31 (half=1)
// odd-positioned ones; each lane loads float2 = features (2*fl, 2*fl+1).
// Caller defines: int half = lane>>4, fl = lane&15; float2 acc2 = {0,0}.
#define WGATHER2(BASEPTR, COMP)                                             \
    for (int cbase = 0; cbase < cnt; cbase += 32) {                         \
        int rem = cnt - cbase; if (rem > 32) rem = 32;                      \
        int myidx = (lane < rem) ? g_pair[beg + cbase + lane].COMP : 0;     \
        int t = 0;                                                          \
        for (; t + 7 < rem; t += 8) {                                       \
            int s0 = __shfl_sync(FULLM, myidx, t + half);                   \
            int s1 = __shfl_sync(FULLM, myidx, t + 2 + half);               \
            int s2 = __shfl_sync(FULLM, myidx, t + 4 + half);               \
            int s3 = __shfl_sync(FULLM, myidx, t + 6 + half);               \
            float2 v0 = *(const float2*)(BASEPTR + s0 * 32 + 2 * fl);       \
            float2 v1 = *(const float2*)(BASEPTR + s1 * 32 + 2 * fl);       \
            float2 v2 = *(const float2*)(BASEPTR + s2 * 32 + 2 * fl);       \
            float2 v3 = *(const float2*)(BASEPTR + s3 * 32 + 2 * fl);       \
            acc2.x += (v0.x + v1.x) + (v2.x + v3.x);                        \
            acc2.y += (v0.y + v1.y) + (v2.y + v3.y);                        \
        }                                                                   \
        for (; t + 1 < rem; t += 2) {                                       \
            int ss = __shfl_sync(FULLM, myidx, t + half);                   \
            float2 v = *(const float2*)(BASEPTR + ss * 32 + 2 * fl);        \
            acc2.x += v.x; acc2.y += v.y;                                   \
        }                                                                   \
        if (t < rem) {                                                      \
            int ss = __shfl_sync(FULLM, myidx, t);                          \
            if (half == 0) {                                                \
                float2 v = *(const float2*)(BASEPTR + ss * 32 + 2 * fl);    \
                acc2.x += v.x; acc2.y += v.y;                               \
            }                                                               \
        }                                                                   \
    }

// combine halves and remap to 32-wide per-lane value (feature = lane)
#define WCOMBINE(AVAL)                                                      \
    {                                                                       \
        acc2.x += __shfl_xor_sync(FULLM, acc2.x, 16);                       \
        acc2.y += __shfl_xor_sync(FULLM, acc2.y, 16);                       \
        float sx = __shfl_sync(FULLM, acc2.x, lane >> 1);                   \
        float sy = __shfl_sync(FULLM, acc2.y, lane >> 1);                   \
        AVAL = (lane & 1) ? sy : sx;                                        \
    }

// ---------------- build z0 = [nf | e2n] @ W0 ----------------
__global__ void k_build0(const float* __restrict__ nf, const float* __restrict__ ef,
                         const float* __restrict__ W0) {
    __shared__ float Ws[D0 * DL];
    __shared__ float agg[8][D0];
    int tid = threadIdx.x;
    for (int i = tid; i < D0 * DL; i += 256) Ws[i] = W0[i];
    __syncthreads();
    int w = tid >> 5, lane = tid & 31;
    int half = lane >> 4, fl = lane & 15;
    int n = blockIdx.x * 8 + w;
    float f0 = nf[n * DNODE + lane];
    float f1 = nf[n * DNODE + 32 + lane];
    int cnt = g_cnt[n]; if (cnt > BCAP) cnt = BCAP;
    int beg = n * BCAP;
    float2 acc2 = make_float2(0.f, 0.f);
    WGATHER2(ef, y)
    float aval;
    WCOMBINE(aval)
    agg[w][lane] = f0; agg[w][32 + lane] = f1; agg[w][64 + lane] = aval;
    __syncwarp();
    float z = 0.f;
#pragma unroll
    for (int d = 0; d < D0; d++) z += agg[w][d] * Ws[d * DL + lane];
    g_zA[n * DL + lane] = z;
}

// ---------------- gather z + tanh + project to next z (32->32) ----------------
__global__ void k_gather32(int insel, int outsel, int hcat_off,
                           const float* __restrict__ b, const float* __restrict__ Wn) {
    __shared__ float Ws[DL * DL];
    __shared__ float bs[DL];
    __shared__ float vals[8][DL];
    int tid = threadIdx.x;
    for (int i = tid; i < DL * DL; i += 256) Ws[i] = Wn[i];
    if (tid < DL) bs[tid] = b[tid];
    __syncthreads();
    int w = tid >> 5, lane = tid & 31;
    int half = lane >> 4, fl = lane & 15;
    int n = blockIdx.x * 8 + w;
    const float* z = zsel(insel);
    float own = z[n * DL + lane];
    int cnt = g_cnt[n]; if (cnt > BCAP) cnt = BCAP;
    int beg = n * BCAP;
    float2 acc2 = make_float2(0.f, 0.f);
    WGATHER2(z, x)
    float aval;
    WCOMBINE(aval)
    float val = tanhf((own + aval + bs[lane]) / ((float)cnt + 1.f));
    g_hcat[n * HSTRIDE + hcat_off + lane] = val;
    vals[w][lane] = val;
    __syncwarp();
    float zn = 0.f;
#pragma unroll
    for (int d = 0; d < DL; d++) zn += vals[w][d] * Ws[d * DL + lane];
    zsel(outsel)[n * DL + lane] = zn;
}

// ---------------- gather z + tanh + project to scalar (32->1) ----------------
__global__ void k_gather_p1(int insel, const float* __restrict__ b,
                            const float* __restrict__ W3) {
    int tid = threadIdx.x;
    int w = tid >> 5, lane = tid & 31;
    int half = lane >> 4, fl = lane & 15;
    int n = blockIdx.x * 8 + w;
    const float* z = zsel(insel);
    float own = z[n * DL + lane];
    int cnt = g_cnt[n]; if (cnt > BCAP) cnt = BCAP;
    int beg = n * BCAP;
    float2 acc2 = make_float2(0.f, 0.f);
    WGATHER2(z, x)
    float aval;
    WCOMBINE(aval)
    float val = tanhf((own + aval + b[lane]) / ((float)cnt + 1.f));
    g_hcat[n * HSTRIDE + 64 + lane] = val;
    float v = val * W3[lane];
#pragma unroll
    for (int off = 16; off > 0; off >>= 1) v += __shfl_xor_sync(FULLM, v, off);
    if (lane == 0) g_z3[n] = v;
}

// ---------------- fused: ch96 gather + topk + head ----------------
__global__ void k_tail(const float* __restrict__ b3,
                       const float* __restrict__ cw1, const float* __restrict__ cb1,
                       const float* __restrict__ cw2, const float* __restrict__ cb2,
                       const float* __restrict__ ow,  const float* __restrict__ ob,
                       float* __restrict__ out) {
    __shared__ float ch96[NPER];
    __shared__ float v[NPER];
    __shared__ int   ix[NPER];
    __shared__ float pooled[KTOP][TOTALF];
    __shared__ float c1s[C1N][KTOP];
    __shared__ float c1p[C1N][PLEN];
    __shared__ float c2s[DENSE];
    int g = blockIdx.x, tid = threadIdx.x;      // 256 threads

    // ---- channel 96: scalar gather of z3 over neighbors ----
    float bb = b3[0];
#pragma unroll
    for (int half = 0; half < 2; half++) {
        int i = tid + half * 256;
        int n = g * NPER + i;
        float a = g_z3[n];
        int cnt = g_cnt[n]; if (cnt > BCAP) cnt = BCAP;
        int beg = n * BCAP, end = beg + cnt;
        int j = beg;
        float a1 = 0.f, a2 = 0.f, a3 = 0.f;
        for (; j + 3 < end; j += 4) {
            a  += g_z3[g_pair[j].x];
            a1 += g_z3[g_pair[j+1].x];
            a2 += g_z3[g_pair[j+2].x];
            a3 += g_z3[g_pair[j+3].x];
        }
        for (; j < end; j++) a += g_z3[g_pair[j].x];
        a = (a + a1) + (a2 + a3);
        float cv = tanhf((a + bb) / ((float)cnt + 1.f));
        ch96[i] = cv;
        v[i] = cv;
        ix[i] = i;
    }
    __syncthreads();

    // ---- bitonic top-K (value desc, index asc ties) ----
    for (int k = 2; k <= NPER; k <<= 1) {
        for (int j = k >> 1; j > 0; j >>= 1) {
            for (int i = tid; i < NPER; i += 256) {
                int p = i ^ j;
                if (p > i) {
                    float va = v[i], vb = v[p];
                    int ia = ix[i], ib = ix[p];
                    bool a_first = (va > vb) || (va == vb && ia < ib);
                    bool up = ((i & k) == 0);
                    if (up ? !a_first : a_first) {
                        v[i] = vb; v[p] = va;
                        ix[i] = ib; ix[p] = ia;
                    }
                }
            }
            __syncthreads();
        }
    }

    // ---- gather pooled (ch 0..95 from hcat, ch96 from shared) ----
    for (int t = tid; t < KTOP * HSTRIDE; t += 256) {
        int kk = t / HSTRIDE, d = t - kk * HSTRIDE;
        int node = g * NPER + ix[kk];
        pooled[kk][d] = g_hcat[node * HSTRIDE + d];
    }
    if (tid < KTOP) pooled[tid][96] = ch96[ix[tid]];
    __syncthreads();

    // ---- 1x1 conv + relu ----
    for (int t = tid; t < C1N * KTOP; t += 256) {
        int o = t / KTOP, kk = t - o * KTOP;
        float s = cb1[o];
#pragma unroll 8
        for (int d = 0; d < TOTALF; d++) s += pooled[kk][d] * cw1[o * TOTALF + d];
        c1s[o][kk] = fmaxf(s, 0.f);
    }
    __syncthreads();

    // ---- maxpool /2 ----
    for (int t = tid; t < C1N * PLEN; t += 256) {
        int o = t / PLEN, j = t - o * PLEN;
        c1p[o][j] = fmaxf(c1s[o][2 * j], c1s[o][2 * j + 1]);
    }
    __syncthreads();

    // ---- conv k=5 + relu ----
    for (int t = tid; t < C2N * CONVL; t += 256) {
        int o = t / CONVL, j = t - o * CONVL;
        float s = cb2[o];
#pragma unroll
        for (int i = 0; i < C1N; i++)
#pragma unroll
            for (int u = 0; u < KW; u++)
                s += c1p[i][j + u] * cw2[(o * C1N + i) * KW + u];
        c2s[o * CONVL + j] = fmaxf(s, 0.f);
    }
    __syncthreads();

    // ---- dense 352->128 + relu ----
    if (tid < OUTD) {
        int u = tid;
        float s = ob[u];
#pragma unroll 8
        for (int f = 0; f < DENSE; f++) s += c2s[f] * ow[f * OUTD + u];
        out[g * OUTD + u] = fmaxf(s, 0.f);
    }
}

// ---------------- launch ----------------
extern "C" void kernel_launch(void* const* d_in, const int* in_sizes, int n_in,
                              void* d_out, int out_size) {
    const float* node_feat = (const float*)d_in[0];
    const float* edge_feat = (const float*)d_in[1];
    const int*   edge_src  = (const int*)  d_in[2];
    const int*   edge_dst  = (const int*)  d_in[3];
    const float* W0 = (const float*)d_in[4];
    const float* b0 = (const float*)d_in[5];
    const float* W1 = (const float*)d_in[6];
    const float* b1 = (const float*)d_in[7];
    const float* W2 = (const float*)d_in[8];
    const float* b2 = (const float*)d_in[9];
    const float* W3 = (const float*)d_in[10];
    const float* b3 = (const float*)d_in[11];
    const float* cw1 = (const float*)d_in[12];
    const float* cb1 = (const float*)d_in[13];
    const float* cw2 = (const float*)d_in[14];
    const float* cb2 = (const float*)d_in[15];
    const float* ow  = (const float*)d_in[16];
    const float* ob  = (const float*)d_in[17];
    float* out = (float*)d_out;

    void* cnt_ptr = nullptr;
    cudaGetSymbolAddress(&cnt_ptr, g_cnt);
    cudaMemsetAsync(cnt_ptr, 0, NNODE * sizeof(int), 0);

    k_fillb<<<NEDGE / 4096, 1024>>>(edge_src, edge_dst);

    k_build0   <<<NNODE / 8, 256>>>(node_feat, edge_feat, W0);  // -> zA
    k_gather32 <<<NNODE / 8, 256>>>(0, 1, 0,  b0, W1);          // zA -> hcat0, zB
    k_gather32 <<<NNODE / 8, 256>>>(1, 0, 32, b1, W2);          // zB -> hcat32, zA
    k_gather_p1<<<NNODE / 8, 256>>>(0, b2, W3);                 // zA -> hcat64, z3

    k_tail<<<NG, 256>>>(b3, cw1, cb1, cw2, cb2, ow, ob, out);
}